// round 15
// baseline (speedup 1.0000x reference)
#include <cuda_runtime.h>
#include <cuda_bf16.h>
#include <cstdint>

// Attention_18631568130094: B=4, Sq=2048, Sk=2048, D=1024
// out[b,q,k] = mask[b,k] ? (Q[b,q]·K[b,k])/(|Q[b,q]||K[b,k]|) : -1e9
// Normalization folded into fp8 quantization: prep stores q/|q|, k/|k| as
// e4m3 (fp8 relative error is scale-invariant), so the GEMM accumulator IS
// the score and the epilogue is a mask select.
// R15: R13 pipeline with the NK mainloop fully unrolled (stage addressing
// and swizzle offsets become compile-time constants).

#define B_  4
#define SQ  2048
#define SK  2048
#define DD  1024
#define NEGV -1000000000.0f

// ---------------- device scratch (no cudaMalloc allowed) -------------------
__device__ uint8_t g_q8[(size_t)B_ * SQ * DD];
__device__ uint8_t g_k8[(size_t)B_ * SK * DD];

// ---------------- helpers --------------------------------------------------
__device__ __forceinline__ uint32_t smem_u32(const void* p) {
    uint32_t a;
    asm("{ .reg .u64 t; cvta.to.shared.u64 t, %1; cvt.u32.u64 %0, t; }"
        : "=r"(a) : "l"(p));
    return a;
}
__device__ __forceinline__ void cp_async16(uint32_t s, const void* g) {
    asm volatile("cp.async.cg.shared.global [%0], [%1], 16;" :: "r"(s), "l"(g));
}
#define CP_COMMIT() asm volatile("cp.async.commit_group;" ::: "memory")
#define CP_WAIT(n)  asm volatile("cp.async.wait_group %0;" :: "n"(n) : "memory")

#define LDSM_X4(r0, r1, r2, r3, addr) \
    asm volatile("ldmatrix.sync.aligned.m8n8.x4.shared.b16 {%0,%1,%2,%3}, [%4];" \
        : "=r"(r0), "=r"(r1), "=r"(r2), "=r"(r3) : "r"(addr))

// fp8 e4m3 MMA: m16n8k32, fp32 accumulate.
#define MMA16832(d, a, bfr) \
    asm volatile("mma.sync.aligned.m16n8k32.row.col.f32.e4m3.e4m3.f32 " \
        "{%0,%1,%2,%3}, {%4,%5,%6,%7}, {%8,%9}, {%0,%1,%2,%3};" \
        : "+f"((d)[0]), "+f"((d)[1]), "+f"((d)[2]), "+f"((d)[3]) \
        : "r"((a)[0]), "r"((a)[1]), "r"((a)[2]), "r"((a)[3]), \
          "r"((bfr)[0]), "r"((bfr)[1]))

// pack 4 floats -> 4 e4m3 bytes (x at byte0 .. w at byte3)
__device__ __forceinline__ uint32_t pack_e4m3x4(float x, float y, float z, float w) {
    uint16_t h0, h1;
    asm("cvt.rn.satfinite.e4m3x2.f32 %0, %1, %2;" : "=h"(h0) : "f"(y), "f"(x));
    asm("cvt.rn.satfinite.e4m3x2.f32 %0, %1, %2;" : "=h"(h1) : "f"(w), "f"(z));
    uint32_t r;
    asm("mov.b32 %0, {%1, %2};" : "=r"(r) : "h"(h0), "h"(h1));
    return r;
}

// ---------------------------------------------------------------------------
// Kernel 1: warp-per-row prep. Row (1024 fp32) lives in 32 regs/lane; warp
// shfl-reduce for the norm; normalize + e4m3-pack from registers. No smem,
// no block barriers. 8 rows per 256-thread CTA -> 2048 CTAs.
// ---------------------------------------------------------------------------
__global__ __launch_bounds__(256) void prep_kernel(const float* __restrict__ q,
                                                   const float* __restrict__ k) {
    const int row = blockIdx.x * 8 + (threadIdx.x >> 5);
    const int lane = threadIdx.x & 31;
    const float* src;
    uint8_t* dst8;
    if (row < B_ * SQ) {
        src = q + (size_t)row * DD;
        dst8 = g_q8 + (size_t)row * DD;
    } else {
        int r = row - B_ * SQ;
        src = k + (size_t)r * DD;
        dst8 = g_k8 + (size_t)r * DD;
    }

    const float4* s4 = (const float4*)src;
    float4 v[8];
    #pragma unroll
    for (int i = 0; i < 8; i++) v[i] = s4[lane + i * 32];

    float s = 0.0f;
    #pragma unroll
    for (int i = 0; i < 8; i++)
        s += v[i].x * v[i].x + v[i].y * v[i].y + v[i].z * v[i].z + v[i].w * v[i].w;
    #pragma unroll
    for (int off = 16; off > 0; off >>= 1)
        s += __shfl_xor_sync(0xFFFFFFFFu, s, off);

    const float inv = 1.0f / fmaxf(sqrtf(s), 1e-8f);

    uint32_t* d32 = (uint32_t*)dst8;
    #pragma unroll
    for (int i = 0; i < 8; i++)
        d32[lane + i * 32] =
            pack_e4m3x4(v[i].x * inv, v[i].y * inv, v[i].z * inv, v[i].w * inv);
}

// ---------------------------------------------------------------------------
// Kernel 2: fp8 mma.sync GEMM on pre-normalized operands. CTA tile 128x128,
// BK=128 (fp8), 3-stage cp.async. 8 warps, warp tile 32x64, m16n8k32.
// Mainloop fully unrolled (NK=8). Epilogue: mask select only.
// SMEM stage: A 16KB + B 16KB; 128B rows, xor-swizzled by (row&7).
// ---------------------------------------------------------------------------
#define STAGES 3
#define NK 8                   // 1024 / 128
#define STAGE_BYTES 32768
#define SMEM_TOTAL (STAGES * STAGE_BYTES)

__global__ __launch_bounds__(256, 2) void gemm_mma_kernel(const int* __restrict__ mask,
                                                          float* __restrict__ out) {
    extern __shared__ char smem[];
    const int tid = threadIdx.x;
    const int b = blockIdx.z;
    const int bm = blockIdx.y * 128;
    const int bn = blockIdx.x * 128;

    __shared__ float s_mk[128];     // 0.0 = masked, 1.0 = keep
    if (tid < 128) {
        s_mk[tid] = mask[b * SK + bn + tid] ? 1.0f : 0.0f;
    }

    const uint8_t* Qb = g_q8 + ((size_t)b * SQ + bm) * DD;
    const uint8_t* Kb = g_k8 + ((size_t)b * SK + bn) * DD;

    // load mapping: thread t covers row t/2, chunks (t%2)*4 .. +3 (16B chunks)
    const int lr = tid >> 1;
    const int lc0 = (tid & 1) * 4;
    const uint32_t sb = smem_u32(smem);

    #define LOAD_TILE(slot, it) do {                                           \
        uint32_t sA_ = sb + (slot) * STAGE_BYTES;                              \
        uint32_t sB_ = sA_ + 16384;                                            \
        const uint8_t* gA = Qb + (size_t)lr * DD + (it) * 128 + lc0 * 16;      \
        const uint8_t* gB = Kb + (size_t)lr * DD + (it) * 128 + lc0 * 16;      \
        _Pragma("unroll")                                                      \
        for (int i = 0; i < 4; i++) {                                          \
            int c = lc0 + i;                                                   \
            uint32_t off = lr * 128 + ((c ^ (lr & 7)) * 16);                   \
            cp_async16(sA_ + off, gA + i * 16);                                \
            cp_async16(sB_ + off, gB + i * 16);                                \
        }                                                                      \
    } while (0)

    float acc[2][8][4];
    #pragma unroll
    for (int mf = 0; mf < 2; mf++)
        #pragma unroll
        for (int nf = 0; nf < 8; nf++)
            #pragma unroll
            for (int r = 0; r < 4; r++) acc[mf][nf][r] = 0.0f;

    const int w = tid >> 5, l = tid & 31;
    const int wm = (w & 3) * 32;     // warp m offset
    const int wn = (w >> 2) * 64;    // warp n offset

    LOAD_TILE(0, 0);
    CP_COMMIT();
    LOAD_TILE(1, 1);
    CP_COMMIT();

    uint32_t af[2][2][4];
    uint32_t bfr[2][8][2];

    // fragment fetch for k-subtile kk (one k32 step = 32B) into buffer p
    #define LOAD_FRAGS(p, sA, sB, kk) do {                                     \
        const int ch = (kk) * 2 + (l >> 4);                                    \
        _Pragma("unroll")                                                      \
        for (int mf = 0; mf < 2; mf++) {                                       \
            int row = wm + mf * 16 + (l & 15);                                 \
            uint32_t off = row * 128 + ((ch ^ (row & 7)) * 16);                \
            LDSM_X4(af[p][mf][0], af[p][mf][1], af[p][mf][2], af[p][mf][3],    \
                    (sA) + off);                                               \
        }                                                                      \
        _Pragma("unroll")                                                      \
        for (int nb = 0; nb < 4; nb++) {                                       \
            int row = wn + nb * 16 + (l & 15);                                 \
            uint32_t off = row * 128 + ((ch ^ (row & 7)) * 16);                \
            uint32_t r0, r1, r2, r3;                                           \
            LDSM_X4(r0, r1, r2, r3, (sB) + off);                               \
            bfr[p][2 * nb][0] = r0;     bfr[p][2 * nb][1] = r2;                \
            bfr[p][2 * nb + 1][0] = r1; bfr[p][2 * nb + 1][1] = r3;            \
        }                                                                      \
    } while (0)

    #pragma unroll
    for (int it = 0; it < NK; it++) {
        CP_WAIT(1);
        __syncthreads();
        if (it + 2 < NK) LOAD_TILE((it + 2) % STAGES, it + 2);
        CP_COMMIT();

        uint32_t sA = sb + (it % STAGES) * STAGE_BYTES;
        uint32_t sB = sA + 16384;

        LOAD_FRAGS(0, sA, sB, 0);
        #pragma unroll
        for (int kk = 0; kk < 4; kk++) {
            const int cur = kk & 1;
            if (kk < 3) LOAD_FRAGS(cur ^ 1, sA, sB, kk + 1);
            #pragma unroll
            for (int mf = 0; mf < 2; mf++)
                #pragma unroll
                for (int nf = 0; nf < 8; nf++)
                    MMA16832(acc[mf][nf], af[cur][mf], bfr[cur][nf]);
        }
    }

    // ---- epilogue: mask select only (scores already normalized) ----
    float mk0[8], mk1[8];
    #pragma unroll
    for (int nf = 0; nf < 8; nf++) {
        const int nl = wn + nf * 8 + (l & 3) * 2;
        mk0[nf] = s_mk[nl];
        mk1[nf] = s_mk[nl + 1];
    }

    #pragma unroll
    for (int mf = 0; mf < 2; mf++) {
        #pragma unroll
        for (int half = 0; half < 2; half++) {
            const int m = bm + wm + mf * 16 + (l >> 2) + half * 8;
            float* orow = out + ((size_t)b * SQ + m) * SK + bn;
            #pragma unroll
            for (int nf = 0; nf < 8; nf++) {
                const int nl = wn + nf * 8 + (l & 3) * 2;
                float2 o;
                o.x = (mk0[nf] == 0.0f) ? NEGV : acc[mf][nf][half * 2 + 0];
                o.y = (mk1[nf] == 0.0f) ? NEGV : acc[mf][nf][half * 2 + 1];
                *(float2*)(orow + nl) = o;
            }
        }
    }
}

// ---------------------------------------------------------------------------
extern "C" void kernel_launch(void* const* d_in, const int* in_sizes, int n_in,
                              void* d_out, int out_size) {
    const float* q = (const float*)d_in[0];
    const float* k = (const float*)d_in[1];
    const int* mask = (const int*)d_in[2];
    float* out = (float*)d_out;

    cudaFuncSetAttribute(gemm_mma_kernel,
                         cudaFuncAttributeMaxDynamicSharedMemorySize, SMEM_TOTAL);

    prep_kernel<<<(B_ * SQ + B_ * SK) / 8, 256>>>(q, k);

    dim3 grid(SK / 128, SQ / 128, B_);
    gemm_mma_kernel<<<grid, 256, SMEM_TOTAL>>>(mask, out);
}

// round 16
// speedup vs baseline: 1.6156x; 1.6156x over previous
#include <cuda_runtime.h>
#include <cuda_bf16.h>
#include <cstdint>

// Attention_18631568130094: B=4, Sq=2048, Sk=2048, D=1024
// out[b,q,k] = mask[b,k] ? (Q[b,q]·K[b,k])/(|Q[b,q]||K[b,k]|) : -1e9
// Mask-aware work skipping: ~50% of columns are masked -> constant -1e9 and
// need no GEMM. Pipeline: normalize+fp8 prep; per-batch mask compaction
// (prefix scan); fp8 GEMM over COMPACTED columns only (R13-proven body, B
// rows via index indirection); scatter kernel rebuilds full output.

#define B_  4
#define SQ  2048
#define SK  2048
#define DD  1024
#define NEGV -1000000000.0f

// ---------------- device scratch (no cudaMalloc allowed) -------------------
__device__ uint8_t g_q8[(size_t)B_ * SQ * DD];
__device__ uint8_t g_k8[(size_t)B_ * SK * DD];
__device__ int   g_pos[B_ * SK];     // output slot of column k (if unmasked)
__device__ int   g_idx[B_ * SK];     // j-th unmasked column index (padded w/ 0)
__device__ int   g_nbp[B_];          // unmasked count, padded to mult of 128
__device__ float g_comp[(size_t)B_ * SQ * SK];   // compacted scores

// ---------------- helpers --------------------------------------------------
__device__ __forceinline__ uint32_t smem_u32(const void* p) {
    uint32_t a;
    asm("{ .reg .u64 t; cvta.to.shared.u64 t, %1; cvt.u32.u64 %0, t; }"
        : "=r"(a) : "l"(p));
    return a;
}
__device__ __forceinline__ void cp_async16(uint32_t s, const void* g) {
    asm volatile("cp.async.cg.shared.global [%0], [%1], 16;" :: "r"(s), "l"(g));
}
#define CP_COMMIT() asm volatile("cp.async.commit_group;" ::: "memory")
#define CP_WAIT(n)  asm volatile("cp.async.wait_group %0;" :: "n"(n) : "memory")

#define LDSM_X4(r0, r1, r2, r3, addr) \
    asm volatile("ldmatrix.sync.aligned.m8n8.x4.shared.b16 {%0,%1,%2,%3}, [%4];" \
        : "=r"(r0), "=r"(r1), "=r"(r2), "=r"(r3) : "r"(addr))

// fp8 e4m3 MMA: m16n8k32, fp32 accumulate.
#define MMA16832(d, a, bfr) \
    asm volatile("mma.sync.aligned.m16n8k32.row.col.f32.e4m3.e4m3.f32 " \
        "{%0,%1,%2,%3}, {%4,%5,%6,%7}, {%8,%9}, {%0,%1,%2,%3};" \
        : "+f"((d)[0]), "+f"((d)[1]), "+f"((d)[2]), "+f"((d)[3]) \
        : "r"((a)[0]), "r"((a)[1]), "r"((a)[2]), "r"((a)[3]), \
          "r"((bfr)[0]), "r"((bfr)[1]))

// pack 4 floats -> 4 e4m3 bytes (x at byte0 .. w at byte3)
__device__ __forceinline__ uint32_t pack_e4m3x4(float x, float y, float z, float w) {
    uint16_t h0, h1;
    asm("cvt.rn.satfinite.e4m3x2.f32 %0, %1, %2;" : "=h"(h0) : "f"(y), "f"(x));
    asm("cvt.rn.satfinite.e4m3x2.f32 %0, %1, %2;" : "=h"(h1) : "f"(w), "f"(z));
    uint32_t r;
    asm("mov.b32 %0, {%1, %2};" : "=r"(r) : "h"(h0), "h"(h1));
    return r;
}

// ---------------------------------------------------------------------------
// Kernel 1: warp-per-row prep (proven). Normalize row, store as e4m3.
// ---------------------------------------------------------------------------
__global__ __launch_bounds__(256) void prep_kernel(const float* __restrict__ q,
                                                   const float* __restrict__ k) {
    const int row = blockIdx.x * 8 + (threadIdx.x >> 5);
    const int lane = threadIdx.x & 31;
    const float* src;
    uint8_t* dst8;
    if (row < B_ * SQ) {
        src = q + (size_t)row * DD;
        dst8 = g_q8 + (size_t)row * DD;
    } else {
        int r = row - B_ * SQ;
        src = k + (size_t)r * DD;
        dst8 = g_k8 + (size_t)r * DD;
    }

    const float4* s4 = (const float4*)src;
    float4 v[8];
    #pragma unroll
    for (int i = 0; i < 8; i++) v[i] = s4[lane + i * 32];

    float s = 0.0f;
    #pragma unroll
    for (int i = 0; i < 8; i++)
        s += v[i].x * v[i].x + v[i].y * v[i].y + v[i].z * v[i].z + v[i].w * v[i].w;
    #pragma unroll
    for (int off = 16; off > 0; off >>= 1)
        s += __shfl_xor_sync(0xFFFFFFFFu, s, off);

    const float inv = 1.0f / fmaxf(sqrtf(s), 1e-8f);

    uint32_t* d32 = (uint32_t*)dst8;
    #pragma unroll
    for (int i = 0; i < 8; i++)
        d32[lane + i * 32] =
            pack_e4m3x4(v[i].x * inv, v[i].y * inv, v[i].z * inv, v[i].w * inv);
}

// ---------------------------------------------------------------------------
// Kernel 2: per-batch mask compaction via block prefix scan. 1024 threads,
// 2 mask entries each. Outputs pos[], idx[] (padded), nbp (padded count).
// ---------------------------------------------------------------------------
__global__ __launch_bounds__(1024) void compact_kernel(const int* __restrict__ mask) {
    const int b = blockIdx.x;
    const int t = threadIdx.x;           // 0..1023
    const int k0 = 2 * t, k1 = 2 * t + 1;
    const int v0 = (mask[b * SK + k0] != 0);
    const int v1 = (mask[b * SK + k1] != 0);
    const int tsum = v0 + v1;

    const int lane = t & 31, wid = t >> 5;
    int incl = tsum;
    #pragma unroll
    for (int off = 1; off < 32; off <<= 1) {
        int n = __shfl_up_sync(0xFFFFFFFFu, incl, off);
        if (lane >= off) incl += n;
    }
    __shared__ int wsum[32];
    __shared__ int s_nb;
    if (lane == 31) wsum[wid] = incl;
    __syncthreads();
    if (wid == 0) {
        int wv = wsum[lane];
        #pragma unroll
        for (int off = 1; off < 32; off <<= 1) {
            int n = __shfl_up_sync(0xFFFFFFFFu, wv, off);
            if (lane >= off) wv += n;
        }
        wsum[lane] = wv;                 // inclusive warp prefix
    }
    __syncthreads();
    const int base = (wid > 0 ? wsum[wid - 1] : 0) + (incl - tsum);  // excl prefix

    g_pos[b * SK + k0] = base;
    g_pos[b * SK + k1] = base + v0;
    if (v0) g_idx[b * SK + base] = k0;
    if (v1) g_idx[b * SK + base + v0] = k1;

    if (t == 1023) s_nb = base + tsum;   // total unmasked count
    __syncthreads();
    const int nb = s_nb;
    if (t == 0) g_nbp[b] = (nb + 127) & ~127;
    for (int j = nb + t; j < SK; j += 1024) g_idx[b * SK + j] = 0;  // pad
}

// ---------------------------------------------------------------------------
// Kernel 3: fp8 mma.sync GEMM over compacted columns. R13-proven pipeline:
// CTA tile 128x128, BK=128, 3-stage cp.async, 8 warps, warp tile 32x64,
// m16n8k32. B rows fetched via idx indirection. CTAs past the padded
// column count exit immediately. Epilogue: plain store to g_comp.
// ---------------------------------------------------------------------------
#define STAGES 3
#define NK 8                   // 1024 / 128
#define STAGE_BYTES 32768
#define SMEM_TOTAL (STAGES * STAGE_BYTES)

__global__ __launch_bounds__(256, 2) void gemm_mma_kernel() {
    const int b = blockIdx.z;
    const int bn = blockIdx.x * 128;
    if (bn >= g_nbp[b]) return;          // uniform early exit, before any barrier

    extern __shared__ char smem[];
    const int tid = threadIdx.x;
    const int bm = blockIdx.y * 128;

    const uint8_t* Qb = g_q8 + ((size_t)b * SQ + bm) * DD;

    // load mapping: thread t covers row t/2, chunks (t%2)*4 .. +3 (16B chunks)
    const int lr = tid >> 1;
    const int lc0 = (tid & 1) * 4;
    const uint32_t sb = smem_u32(smem);

    // B row indirection: compacted column (bn+lr) -> original K row
    const int krow = g_idx[b * SK + bn + lr];
    const uint8_t* gBrow = g_k8 + ((size_t)b * SK + krow) * DD;

    #define LOAD_TILE(slot, it) do {                                           \
        uint32_t sA_ = sb + (slot) * STAGE_BYTES;                              \
        uint32_t sB_ = sA_ + 16384;                                            \
        const uint8_t* gA = Qb + (size_t)lr * DD + (it) * 128 + lc0 * 16;      \
        const uint8_t* gB = gBrow + (it) * 128 + lc0 * 16;                     \
        _Pragma("unroll")                                                      \
        for (int i = 0; i < 4; i++) {                                          \
            int c = lc0 + i;                                                   \
            uint32_t off = lr * 128 + ((c ^ (lr & 7)) * 16);                   \
            cp_async16(sA_ + off, gA + i * 16);                                \
            cp_async16(sB_ + off, gB + i * 16);                                \
        }                                                                      \
    } while (0)

    float acc[2][8][4];
    #pragma unroll
    for (int mf = 0; mf < 2; mf++)
        #pragma unroll
        for (int nf = 0; nf < 8; nf++)
            #pragma unroll
            for (int r = 0; r < 4; r++) acc[mf][nf][r] = 0.0f;

    const int w = tid >> 5, l = tid & 31;
    const int wm = (w & 3) * 32;     // warp m offset
    const int wn = (w >> 2) * 64;    // warp n offset

    LOAD_TILE(0, 0);
    CP_COMMIT();
    LOAD_TILE(1, 1);
    CP_COMMIT();

    uint32_t af[2][2][4];
    uint32_t bfr[2][8][2];

    // fragment fetch for k-subtile kk (one k32 step = 32B) into buffer p
    #define LOAD_FRAGS(p, sA, sB, kk) do {                                     \
        const int ch = (kk) * 2 + (l >> 4);                                    \
        _Pragma("unroll")                                                      \
        for (int mf = 0; mf < 2; mf++) {                                       \
            int row = wm + mf * 16 + (l & 15);                                 \
            uint32_t off = row * 128 + ((ch ^ (row & 7)) * 16);                \
            LDSM_X4(af[p][mf][0], af[p][mf][1], af[p][mf][2], af[p][mf][3],    \
                    (sA) + off);                                               \
        }                                                                      \
        _Pragma("unroll")                                                      \
        for (int nb2 = 0; nb2 < 4; nb2++) {                                    \
            int row = wn + nb2 * 16 + (l & 15);                                \
            uint32_t off = row * 128 + ((ch ^ (row & 7)) * 16);                \
            uint32_t r0, r1, r2, r3;                                           \
            LDSM_X4(r0, r1, r2, r3, (sB) + off);                               \
            bfr[p][2 * nb2][0] = r0;     bfr[p][2 * nb2][1] = r2;              \
            bfr[p][2 * nb2 + 1][0] = r1; bfr[p][2 * nb2 + 1][1] = r3;          \
        }                                                                      \
    } while (0)

    for (int it = 0; it < NK; it++) {
        CP_WAIT(1);
        __syncthreads();
        if (it + 2 < NK) LOAD_TILE((it + 2) % STAGES, it + 2);
        CP_COMMIT();

        uint32_t sA = sb + (it % STAGES) * STAGE_BYTES;
        uint32_t sB = sA + 16384;

        LOAD_FRAGS(0, sA, sB, 0);
        #pragma unroll
        for (int kk = 0; kk < 4; kk++) {
            const int cur = kk & 1;
            if (kk < 3) LOAD_FRAGS(cur ^ 1, sA, sB, kk + 1);
            #pragma unroll
            for (int mf = 0; mf < 2; mf++)
                #pragma unroll
                for (int nf = 0; nf < 8; nf++)
                    MMA16832(acc[mf][nf], af[cur][mf], bfr[cur][nf]);
        }
    }

    // ---- epilogue: plain store (all compacted columns are unmasked) ----
    #pragma unroll
    for (int mf = 0; mf < 2; mf++) {
        #pragma unroll
        for (int half = 0; half < 2; half++) {
            const int m = bm + wm + mf * 16 + (l >> 2) + half * 8;
            float* orow = g_comp + ((size_t)b * SQ + m) * SK + bn;
            #pragma unroll
            for (int nf = 0; nf < 8; nf++) {
                const int nl = wn + nf * 8 + (l & 3) * 2;
                *(float2*)(orow + nl) =
                    make_float2(acc[mf][nf][half * 2 + 0],
                                acc[mf][nf][half * 2 + 1]);
            }
        }
    }
}

// ---------------------------------------------------------------------------
// Kernel 4: scatter compacted scores into the full output; masked -> NEG.
// One CTA per output row; coalesced float4 stores. mask/pos rows are tiny
// and L1/L2-resident; comp reads are near-sequential (pos is monotonic).
// ---------------------------------------------------------------------------
__global__ __launch_bounds__(256) void scatter_kernel(const int* __restrict__ mask,
                                                      float* __restrict__ out) {
    const int row = blockIdx.x;              // 0..8191
    const int b = row >> 11, m = row & 2047;
    const int t = threadIdx.x;
    const float* comp = g_comp + ((size_t)b * SQ + m) * SK;
    float* orow = out + ((size_t)b * SQ + m) * SK;
    const int* mrow = mask + b * SK;
    const int* prow = g_pos + b * SK;

    const int k0 = t * 8;
    int4 mk0 = *(const int4*)&mrow[k0];
    int4 mk1 = *(const int4*)&mrow[k0 + 4];
    int4 p0 = *(const int4*)&prow[k0];
    int4 p1 = *(const int4*)&prow[k0 + 4];

    float4 o0, o1;
    o0.x = mk0.x ? comp[p0.x] : NEGV;
    o0.y = mk0.y ? comp[p0.y] : NEGV;
    o0.z = mk0.z ? comp[p0.z] : NEGV;
    o0.w = mk0.w ? comp[p0.w] : NEGV;
    o1.x = mk1.x ? comp[p1.x] : NEGV;
    o1.y = mk1.y ? comp[p1.y] : NEGV;
    o1.z = mk1.z ? comp[p1.z] : NEGV;
    o1.w = mk1.w ? comp[p1.w] : NEGV;

    *(float4*)&orow[k0] = o0;
    *(float4*)&orow[k0 + 4] = o1;
}

// ---------------------------------------------------------------------------
extern "C" void kernel_launch(void* const* d_in, const int* in_sizes, int n_in,
                              void* d_out, int out_size) {
    const float* q = (const float*)d_in[0];
    const float* k = (const float*)d_in[1];
    const int* mask = (const int*)d_in[2];
    float* out = (float*)d_out;

    cudaFuncSetAttribute(gemm_mma_kernel,
                         cudaFuncAttributeMaxDynamicSharedMemorySize, SMEM_TOTAL);

    prep_kernel<<<(B_ * SQ + B_ * SK) / 8, 256>>>(q, k);
    compact_kernel<<<B_, 1024>>>(mask);

    dim3 grid(SK / 128, SQ / 128, B_);
    gemm_mma_kernel<<<grid, 256, SMEM_TOTAL>>>();

    scatter_kernel<<<B_ * SQ, 256>>>(mask, out);
}